// round 2
// baseline (speedup 1.0000x reference)
#include <cuda_runtime.h>

#define LLEN 1024
#define NB   64
#define TILE 128

// ---- device scratch (no allocations allowed) ----
__device__ float g_cat [NB * 192 * LLEN];
__device__ float g_dec [NB * 192 * LLEN];
__device__ float g_encU[NB * 64  * LLEN];
__device__ int   g_ids [NB];

typedef unsigned long long u64;

__device__ __forceinline__ u64 pack2(float a, float b) {
    u64 r; asm("mov.b64 %0, {%1, %2};" : "=l"(r) : "f"(a), "f"(b)); return r;
}
__device__ __forceinline__ void fma2(u64& d, u64 a, u64 b) {
    asm("fma.rn.f32x2 %0, %1, %2, %0;" : "+l"(d) : "l"(a), "l"(b));
}
__device__ __forceinline__ void unpack2(u64 v, float& lo, float& hi) {
    asm("mov.b64 {%0, %1}, %2;" : "=f"(lo), "=f"(hi) : "l"(v));
}

// ------------------------------------------------------------------
__global__ void ids_kernel(const float* __restrict__ x) {
    int b = threadIdx.x;
    if (b < NB) g_ids[b] = (int)x[(long)b * (LLEN + 1) + LLEN];
}

// ------------------------------------------------------------------
// Fused block: y = relu(W2 @ relu(dilated_conv5(x, W1) + b1) + b2)
// conv1: CIN -> 128 (k=5, dilation DIL), conv2: 128 -> 32 (1x1)
// Grid (L/TILE, B), 512 threads. f32x2 packed FMA over output-channel pairs.
// smem: xs[CIN][256] | ws1[CCH][5][128] | hs[128][TILE] | ws2[128][34] | b1s | b2s
// ------------------------------------------------------------------
template<int CIN, int DIL>
__global__ void __launch_bounds__(512, 1)
block_kernel(const float* __restrict__ xin, long in_samp_stride, int in_ch_stride,
             const float* __restrict__ w1, const float* __restrict__ b1,
             const float* __restrict__ w2, const float* __restrict__ b2,
             float* __restrict__ yout, long out_samp_stride,
             const int* __restrict__ ids,
             long w1_cs, long b1_cs, long w2_cs, long b2_cs)
{
    constexpr int CCH = (CIN < 16) ? CIN : 16;
    extern __shared__ float sm[];
    float* xs  = sm;                       // CIN * 256
    float* ws1 = xs  + CIN * 256;          // CCH * 5 * 128   [cil][t][co]
    float* hs  = ws1 + CCH * 640;          // 128 * TILE
    float* ws2 = hs  + 128 * TILE;         // 128 * 34        [k][co2] (pad 34)
    float* b1s = ws2 + 128 * 34;           // 128
    float* b2s = b1s + 128;                // 32

    const int b    = blockIdx.y;
    const int l0   = blockIdx.x * TILE;
    const int tid  = threadIdx.x;
    const int warp = tid >> 5;
    const int ln   = tid & 31;

    const float* w1p = w1;
    const float* b1p = b1;
    const float* w2p = w2;
    const float* b2p = b2;
    if (ids) {
        int c = ids[b];
        w1p += (long)c * w1_cs;  b1p += (long)c * b1_cs;
        w2p += (long)c * w2_cs;  b2p += (long)c * b2_cs;
    }

    // ---- stage input tile (halo 2*DIL each side, zero-padded) ----
    const float* xb = xin + (long)b * in_samp_stride;
    for (int i = tid; i < CIN * 256; i += 512) {
        int ci = i >> 8, j = i & 255;
        int pos = l0 - 2 * DIL + j;
        xs[i] = (pos >= 0 && pos < LLEN) ? xb[(long)ci * in_ch_stride + pos] : 0.f;
    }
    if (tid < 128) b1s[tid] = b1p[tid];
    if (tid < 32)  b2s[tid] = b2p[tid];
    // ws2: [k][co2] with pad 34 (keeps k*34 even -> 8B-aligned pairs)
    for (int i = tid; i < 32 * 128; i += 512) {
        int co = i >> 7, k = i & 127;
        ws2[k * 34 + co] = w2p[i];
    }

    // ---- conv1: warp owns co = warp*8 .. +8 (4 pairs), lane owns l = ln+32*i ----
    u64 accp[4][4];
    #pragma unroll
    for (int cp = 0; cp < 4; cp++)
        #pragma unroll
        for (int i = 0; i < 4; i++) accp[cp][i] = 0ull;

    for (int ci0 = 0; ci0 < CIN; ci0 += CCH) {
        __syncthreads();
        // stage ws1 chunk, layout [cil][t][co]
        for (int i = tid; i < CCH * 640; i += 512) {
            int cil = i / 640;
            int r   = i - cil * 640;
            int t   = r >> 7;
            int co  = r & 127;
            ws1[i] = w1p[(long)co * (CIN * 5) + (ci0 + cil) * 5 + t];
        }
        __syncthreads();
        #pragma unroll
        for (int cil = 0; cil < CCH; cil++) {
            const float* xrow = xs + (ci0 + cil) * 256 + ln;
            const float* wrow = ws1 + cil * 640 + warp * 8;
            #pragma unroll
            for (int t = 0; t < 5; t++) {
                u64 xp[4];
                #pragma unroll
                for (int i = 0; i < 4; i++) {
                    float xv = xrow[32 * i + t * DIL];
                    xp[i] = pack2(xv, xv);
                }
                #pragma unroll
                for (int cp = 0; cp < 4; cp++) {
                    u64 wp = *(const u64*)(wrow + t * 128 + 2 * cp);
                    #pragma unroll
                    for (int i = 0; i < 4; i++) fma2(accp[cp][i], wp, xp[i]);
                }
            }
        }
    }
    __syncthreads();
    // ---- bias + relu -> hs ----
    #pragma unroll
    for (int cp = 0; cp < 4; cp++) {
        int co = warp * 8 + 2 * cp;
        float bb0 = b1s[co], bb1 = b1s[co + 1];
        #pragma unroll
        for (int i = 0; i < 4; i++) {
            float v0, v1; unpack2(accp[cp][i], v0, v1);
            v0 += bb0; v1 += bb1;
            hs[co * TILE + ln + 32 * i]       = v0 > 0.f ? v0 : 0.f;
            hs[(co + 1) * TILE + ln + 32 * i] = v1 > 0.f ? v1 : 0.f;
        }
    }
    __syncthreads();

    // ---- conv2 (1x1, 128 -> 32): warp owns pair (2*warp, 2*warp+1) ----
    u64 a2p[4];
    #pragma unroll
    for (int i = 0; i < 4; i++) a2p[i] = 0ull;

    #pragma unroll 4
    for (int k = 0; k < 128; k++) {
        u64 wp = *(const u64*)(ws2 + k * 34 + warp * 2);
        #pragma unroll
        for (int i = 0; i < 4; i++) {
            float xv = hs[k * TILE + ln + 32 * i];
            fma2(a2p[i], wp, pack2(xv, xv));
        }
    }

    float* yb = yout + (long)b * out_samp_stride;
    {
        int co2 = warp * 2;
        float bb0 = b2s[co2], bb1 = b2s[co2 + 1];
        #pragma unroll
        for (int i = 0; i < 4; i++) {
            float v0, v1; unpack2(a2p[i], v0, v1);
            v0 += bb0; v1 += bb1;
            yb[(long)co2 * LLEN + l0 + ln + 32 * i]       = v0 > 0.f ? v0 : 0.f;
            yb[(long)(co2 + 1) * LLEN + l0 + ln + 32 * i] = v1 > 0.f ? v1 : 0.f;
        }
    }
}

// ------------------------------------------------------------------
// compress conv (192 -> 64, 1x1) fused with avgpool(2)+repeat(2)
// ------------------------------------------------------------------
__global__ void __launch_bounds__(512, 1)
comp_kernel(const float* __restrict__ cat, const float* __restrict__ cw,
            const float* __restrict__ cb, float* __restrict__ out)
{
    extern __shared__ float sm[];
    float* xs  = sm;                  // 192 * 128
    float* ws  = xs + 192 * 128;      // 192 * 66   [k][co] pad 66
    float* cbs = ws + 192 * 66;       // 64

    const int b    = blockIdx.y;
    const int l0   = blockIdx.x * TILE;
    const int tid  = threadIdx.x;
    const int warp = tid >> 5;
    const int ln   = tid & 31;

    const float* catb = cat + (long)b * 192 * LLEN;
    for (int i = tid; i < 192 * 128; i += 512) {
        int ch = i >> 7, j = i & 127;
        xs[i] = catb[(long)ch * LLEN + l0 + j];
    }
    for (int i = tid; i < 64 * 192; i += 512) {
        int co = i / 192, k = i - co * 192;
        ws[k * 66 + co] = cw[i];
    }
    if (tid < 64) cbs[tid] = cb[tid];
    __syncthreads();

    // warp owns co = warp*4 .. +4 (2 pairs)
    u64 accp[2][4];
    #pragma unroll
    for (int cp = 0; cp < 2; cp++)
        #pragma unroll
        for (int i = 0; i < 4; i++) accp[cp][i] = 0ull;

    #pragma unroll 4
    for (int k = 0; k < 192; k++) {
        u64 wp0 = *(const u64*)(ws + k * 66 + warp * 4);
        u64 wp1 = *(const u64*)(ws + k * 66 + warp * 4 + 2);
        #pragma unroll
        for (int i = 0; i < 4; i++) {
            float xv = xs[k * 128 + ln + 32 * i];
            u64 xp = pack2(xv, xv);
            fma2(accp[0][i], wp0, xp);
            fma2(accp[1][i], wp1, xp);
        }
    }

    float* ob = out + (long)b * 64 * LLEN;
    #pragma unroll
    for (int cp = 0; cp < 2; cp++) {
        int co = warp * 4 + 2 * cp;
        float bb0 = cbs[co], bb1 = cbs[co + 1];
        #pragma unroll
        for (int i = 0; i < 4; i++) {
            float v0, v1; unpack2(accp[cp][i], v0, v1);
            v0 += bb0; v1 += bb1;
            // avgpool(2)+nearest upsample(2): adjacent lanes hold the l pair
            float p0 = __shfl_xor_sync(0xffffffffu, v0, 1);
            float p1 = __shfl_xor_sync(0xffffffffu, v1, 1);
            ob[(long)co * LLEN + l0 + ln + 32 * i]       = 0.5f * (v0 + p0);
            ob[(long)(co + 1) * LLEN + l0 + ln + 32 * i] = 0.5f * (v1 + p1);
        }
    }
}

// ------------------------------------------------------------------
// final per-sample 1x1 conv: 192 -> 1, weights selected by combination id
// ------------------------------------------------------------------
__global__ void __launch_bounds__(256, 1)
final_kernel(const float* __restrict__ dec, const float* __restrict__ cw,
             const float* __restrict__ cbv, float* __restrict__ out)
{
    __shared__ float ws[192];
    const int b   = blockIdx.x;
    const int tid = threadIdx.x;
    const int c   = g_ids[b];
    if (tid < 192) ws[tid] = cw[(long)c * 192 + tid];
    __syncthreads();
    const float bb = cbv[c];
    const float* db = dec + (long)b * 192 * LLEN;
    for (int l = tid; l < LLEN; l += 256) {
        float s = bb;
        #pragma unroll 8
        for (int ch = 0; ch < 192; ch++) s = fmaf(ws[ch], db[(long)ch * LLEN + l], s);
        out[(long)b * LLEN + l] = s;
    }
}

// ------------------------------------------------------------------
static constexpr int smem_block(int cin) {
    int cch = cin < 16 ? cin : 16;
    return (cin * 256 + cch * 640 + 128 * TILE + 128 * 34 + 160) * 4;
}
static constexpr int SMEM_C = (192 * 128 + 192 * 66 + 64) * 4;

template<int CIN, int DIL>
static void launch_block(const float* xin, long iss, int ics,
                         const float* w1, const float* b1,
                         const float* w2, const float* b2,
                         float* yout, long oss,
                         const int* ids, long w1cs, long b1cs, long w2cs, long b2cs)
{
    static bool attr_done = false;
    if (!attr_done) {
        cudaFuncSetAttribute(block_kernel<CIN, DIL>,
                             cudaFuncAttributeMaxDynamicSharedMemorySize, smem_block(CIN));
        attr_done = true;
    }
    dim3 grid(LLEN / TILE, NB);
    block_kernel<CIN, DIL><<<grid, 512, smem_block(CIN)>>>(
        xin, iss, ics, w1, b1, w2, b2, yout, oss, ids, w1cs, b1cs, w2cs, b2cs);
}

extern "C" void kernel_launch(void* const* d_in, const int* in_sizes, int n_in,
                              void* d_out, int out_size)
{
    const float* x        = (const float*)d_in[0];
    const float* enc0_w1  = (const float*)d_in[1];
    const float* enc0_b1  = (const float*)d_in[2];
    const float* enc0_w2  = (const float*)d_in[3];
    const float* enc0_b2  = (const float*)d_in[4];
    const float* enc_w1   = (const float*)d_in[5];
    const float* enc_b1   = (const float*)d_in[6];
    const float* enc_w2   = (const float*)d_in[7];
    const float* enc_b2   = (const float*)d_in[8];
    const float* comp_w   = (const float*)d_in[9];
    const float* comp_b   = (const float*)d_in[10];
    const float* decf0_w1 = (const float*)d_in[11];
    const float* decf0_b1 = (const float*)d_in[12];
    const float* decf0_w2 = (const float*)d_in[13];
    const float* decf0_b2 = (const float*)d_in[14];
    const float* decf_w1  = (const float*)d_in[15];
    const float* decf_b1  = (const float*)d_in[16];
    const float* decf_w2  = (const float*)d_in[17];
    const float* decf_b2  = (const float*)d_in[18];
    const float* decv_w1  = (const float*)d_in[19];
    const float* decv_b1  = (const float*)d_in[20];
    const float* decv_w2  = (const float*)d_in[21];
    const float* decv_b2  = (const float*)d_in[22];
    const float* decv_cw  = (const float*)d_in[23];
    const float* decv_cb  = (const float*)d_in[24];
    float* out = (float*)d_out;

    float *cat, *dec, *encU;
    int* idsp;
    cudaGetSymbolAddress((void**)&cat,  g_cat);
    cudaGetSymbolAddress((void**)&dec,  g_dec);
    cudaGetSymbolAddress((void**)&encU, g_encU);
    cudaGetSymbolAddress((void**)&idsp, g_ids);

    cudaFuncSetAttribute(comp_kernel, cudaFuncAttributeMaxDynamicSharedMemorySize, SMEM_C);

    const long SS = (long)192 * LLEN;

    ids_kernel<<<1, 64>>>(x);

    // ---- encoder ----
    launch_block<1, 1>(x, (long)(LLEN + 1), 0,
                       enc0_w1, enc0_b1, enc0_w2, enc0_b2,
                       cat, SS, nullptr, 0, 0, 0, 0);
    launch_block<32, 2>(cat + 0 * 32 * LLEN, SS, LLEN,
                        enc_w1 + 0 * 20480, enc_b1 + 0 * 128, enc_w2 + 0 * 4096, enc_b2 + 0 * 32,
                        cat + 1 * 32 * LLEN, SS, nullptr, 0, 0, 0, 0);
    launch_block<32, 4>(cat + 1 * 32 * LLEN, SS, LLEN,
                        enc_w1 + 1 * 20480, enc_b1 + 1 * 128, enc_w2 + 1 * 4096, enc_b2 + 1 * 32,
                        cat + 2 * 32 * LLEN, SS, nullptr, 0, 0, 0, 0);
    launch_block<32, 8>(cat + 2 * 32 * LLEN, SS, LLEN,
                        enc_w1 + 2 * 20480, enc_b1 + 2 * 128, enc_w2 + 2 * 4096, enc_b2 + 2 * 32,
                        cat + 3 * 32 * LLEN, SS, nullptr, 0, 0, 0, 0);
    launch_block<32, 16>(cat + 3 * 32 * LLEN, SS, LLEN,
                         enc_w1 + 3 * 20480, enc_b1 + 3 * 128, enc_w2 + 3 * 4096, enc_b2 + 3 * 32,
                         cat + 4 * 32 * LLEN, SS, nullptr, 0, 0, 0, 0);
    launch_block<32, 32>(cat + 4 * 32 * LLEN, SS, LLEN,
                         enc_w1 + 4 * 20480, enc_b1 + 4 * 128, enc_w2 + 4 * 4096, enc_b2 + 4 * 32,
                         cat + 5 * 32 * LLEN, SS, nullptr, 0, 0, 0, 0);

    // ---- compress + pool + upsample ----
    {
        dim3 grid(LLEN / TILE, NB);
        comp_kernel<<<grid, 512, SMEM_C>>>(cat, comp_w, comp_b, encU);
    }

    // ---- fixed decoder ----
    launch_block<64, 32>(encU, (long)64 * LLEN, LLEN,
                         decf0_w1, decf0_b1, decf0_w2, decf0_b2,
                         dec, SS, nullptr, 0, 0, 0, 0);
    launch_block<32, 16>(dec + 0 * 32 * LLEN, SS, LLEN,
                         decf_w1 + 0 * 20480, decf_b1 + 0 * 128, decf_w2 + 0 * 4096, decf_b2 + 0 * 32,
                         dec + 1 * 32 * LLEN, SS, nullptr, 0, 0, 0, 0);
    launch_block<32, 8>(dec + 1 * 32 * LLEN, SS, LLEN,
                        decf_w1 + 1 * 20480, decf_b1 + 1 * 128, decf_w2 + 1 * 4096, decf_b2 + 1 * 32,
                        dec + 2 * 32 * LLEN, SS, nullptr, 0, 0, 0, 0);
    launch_block<32, 4>(dec + 2 * 32 * LLEN, SS, LLEN,
                        decf_w1 + 2 * 20480, decf_b1 + 2 * 128, decf_w2 + 2 * 4096, decf_b2 + 2 * 32,
                        dec + 3 * 32 * LLEN, SS, nullptr, 0, 0, 0, 0);

    // ---- variable decoder: only the per-sample selected combination ----
    launch_block<32, 2>(dec + 3 * 32 * LLEN, SS, LLEN,
                        decv_w1 + 0 * 20480, decv_b1 + 0 * 128, decv_w2 + 0 * 4096, decv_b2 + 0 * 32,
                        dec + 4 * 32 * LLEN, SS,
                        idsp, 40960, 256, 8192, 64);
    launch_block<32, 1>(dec + 4 * 32 * LLEN, SS, LLEN,
                        decv_w1 + 1 * 20480, decv_b1 + 1 * 128, decv_w2 + 1 * 4096, decv_b2 + 1 * 32,
                        dec + 5 * 32 * LLEN, SS,
                        idsp, 40960, 256, 8192, 64);

    // ---- final 1x1 conv (per-sample weights) ----
    final_kernel<<<NB, 256>>>(dec, decv_cw, decv_cb, out);
}